// round 1
// baseline (speedup 1.0000x reference)
#include <cuda_runtime.h>
#include <cuda_bf16.h>

// Problem constants
constexpr int TIMESTEPS = 1000;
constexpr int B = 4;
constexpr int N = 2048;                       // power of two: row = b*N + i
constexpr long long E = (long long)N * (N - 1) / 2;   // 2,096,128

// Per-batch diffusion constants, produced by prep_kernel, read by loss_kernel.
__device__ float g_flip_t[B];
__device__ float g_flip_p[B];
__device__ float g_flip0;

// Zeroes the output accumulator (d_out is poisoned before timing and the
// graph is replayed, so this must run every launch) and computes the
// per-batch flip probabilities in double precision.
__global__ void prep_kernel(const int* __restrict__ t, float* __restrict__ out) {
    int tid = threadIdx.x;
    if (tid == 0) {
        out[0] = 0.0f;
        g_flip0 = (float)(0.5 * (1.0 - 0.98));
    }
    if (tid < B) {
        int tb = t[tid];
        // Qt[t]  -> flip at index t   (ts = t+1)
        g_flip_t[tid] = (float)(0.5 * (1.0 - pow(0.98, (double)(tb + 1))));
        // Qt[t-1] with JAX negative-index wrap: t=0 -> index 999
        int tm1 = (tb + TIMESTEPS - 1) % TIMESTEPS;
        g_flip_p[tid] = (float)(0.5 * (1.0 - pow(0.98, (double)(tm1 + 1))));
    }
}

// One CTA per (batch, row i). Threads stride the strict lower triangle
// j in [0, i). All three global streams (adj row, u row, q_approx segment)
// are contiguous and coalesced.
__global__ __launch_bounds__(256)
void loss_kernel(const int* __restrict__ adj,
                 const float* __restrict__ u,
                 const float* __restrict__ q,
                 float* __restrict__ out) {
    int row = blockIdx.x;           // 0 .. B*N-1
    int b = row >> 11;              // / N
    int i = row & (N - 1);          // % N

    float flip_t = g_flip_t[b];
    float flip_p = g_flip_p[b];
    float flip0  = g_flip0;
    float omt = 1.0f - flip_t;      // Qt[t][a,a]
    float omp = 1.0f - flip_p;
    float lik_hi = 1.0f - flip0;    // Qt[0][1,1]

    const int*   adj_row = adj + ((size_t)row << 11);
    const float* u_row   = u   + ((size_t)row << 11);
    const float* q_row   = q + (size_t)b * (size_t)E + (((size_t)i * (i - 1)) >> 1);

    float s = 0.0f;
    for (int j = threadIdx.x; j < i; j += 256) {
        int   a  = adj_row[j];
        float uu = u_row[j];
        float x  = q_row[j];

        float probs1 = a ? omt : flip_t;          // Qt[t][a, 1]
        bool  x1     = uu < probs1;               // sampled bit
        float lik1   = x1 ? lik_hi : flip0;       // Qt[0][x1, 1]
        float prior1 = a ? omp : flip_p;          // Qt[t-1][a, 1]
        float evid   = ((a != 0) == x1) ? omt : flip_t;  // Qt[t][a, x1]
        float qt     = lik1 * prior1 / evid;

        // BCE-with-logits: max(x,0) - x*qt + log1p(exp(-|x|))
        s += fmaxf(x, 0.0f) - x * qt + log1pf(expf(-fabsf(x)));
    }

    // Block reduction: warp shuffle + shared, then one scaled atomic per CTA.
    __shared__ float warp_sums[8];
    #pragma unroll
    for (int off = 16; off; off >>= 1) s += __shfl_down_sync(0xffffffffu, s, off);
    int lane = threadIdx.x & 31;
    int wid  = threadIdx.x >> 5;
    if (lane == 0) warp_sums[wid] = s;
    __syncthreads();
    if (wid == 0) {
        s = (lane < 8) ? warp_sums[lane] : 0.0f;
        #pragma unroll
        for (int off = 4; off; off >>= 1) s += __shfl_down_sync(0xffffffffu, s, off);
        if (lane == 0) {
            const float scale = 1.0f / (float)(B * E);
            atomicAdd(out, s * scale);
        }
    }
}

extern "C" void kernel_launch(void* const* d_in, const int* in_sizes, int n_in,
                              void* d_out, int out_size) {
    // metadata order: adj_start (int32), t (int32), u (f32), q_approx (f32)
    const int*   adj = (const int*)d_in[0];
    const int*   t   = (const int*)d_in[1];
    const float* u   = (const float*)d_in[2];
    const float* q   = (const float*)d_in[3];
    float* out = (float*)d_out;

    prep_kernel<<<1, 32>>>(t, out);
    loss_kernel<<<B * N, 256>>>(adj, u, q, out);
}